// round 9
// baseline (speedup 1.0000x reference)
#include <cuda_runtime.h>

#define MAX_N 100000
#define D 64

// Scratch (device globals: sanctioned alternative to cudaMalloc)
__device__ float g_h[MAX_N * D];     // h = x @ W^T
__device__ float g_deg[MAX_N];
__device__ float g_dinv[MAX_N];
__device__ float g_Wt[D * D];        // W transposed: g_Wt[k*64+o] = W[o][k]

// ---------------------------------------------------------------------------
// 1) degree init: every node gets a self-loop -> deg starts at 1
// ---------------------------------------------------------------------------
__global__ void deg_init_kernel(int N4) {
    int i = blockIdx.x * blockDim.x + threadIdx.x;
    if (i < N4) ((float4*)g_deg)[i] = make_float4(1.f, 1.f, 1.f, 1.f);
}

// 2) accumulate in-degree over edge dst (edge_index is int32)
__global__ void deg_acc_kernel(const int* __restrict__ ei, int E) {
    int e = blockIdx.x * blockDim.x + threadIdx.x;
    if (e < E) atomicAdd(&g_deg[ei[E + e]], 1.0f);
}

// 3) transpose W once into gmem so gemm's smem fill is coalesced/conflict-free
__global__ void wt_kernel(const float* __restrict__ W) {
    int i = blockIdx.x * 256 + threadIdx.x;
    if (i < D * D) {
        int o = i >> 6, k = i & 63;
        g_Wt[k * D + o] = W[i];
    }
}

// ---------------------------------------------------------------------------
// 4) GEMM: h[n][o] = sum_k x[n][k] * W[o][k]
//    Retile vs R8: thread = (2 nodes, warp-uniform OCTANT o = wid).
//    Accumulators: 8 u64 (16 regs) -> ~50 regs total -> ~5 blocks/SM,
//    occupancy ~2x of R8's 32-acc version; W LDS stay broadcast.
//    x staged through smem, coalesced + XOR-swizzled (as R8, proven).
//    Epilogue: dinv, h, out = h*dinv^2 + b (covers poisoned out).
// ---------------------------------------------------------------------------
__global__ __launch_bounds__(256)
void gemm_kernel(const float* __restrict__ x,
                 const float* __restrict__ bias,
                 float* __restrict__ out, int N) {
    __shared__ float Ws[D * D];        // Ws[k*64+o], natural layout
    __shared__ float Xs[64 * D];       // 64-node tile, XOR-swizzled float4s

    int tid = threadIdx.x;

    for (int t = tid; t < D * D; t += 256) Ws[t] = g_Wt[t];

    int base = blockIdx.x * 64;
    int rows = N - base; if (rows > 64) rows = 64;
    const float4* xg = (const float4*)(x + (size_t)base * D);
    for (int t = tid; t < rows * 16; t += 256) {
        int r = t >> 4, j = t & 15;
        ((float4*)Xs)[r * 16 + (j ^ (r & 15))] = xg[t];
    }
    __syncthreads();

    int w    = tid >> 5;                 // warp 0..7
    int lane = tid & 31;
    int o    = w;                        // output octant (warp-uniform!)
    int n0 = base + lane;                // node 1
    int n1 = n0 + 32;                    // node 2
    // (N = 100000 is not a multiple of 64; guard in epilogue. Compute reads
    //  Xs rows beyond `rows` only in the last block; those are uninitialized
    //  but results are discarded by the epilogue guard. To keep reads in
    //  bounds Xs is always indexed < 64 rows.)

    unsigned long long a0[4], a1[4];
#pragma unroll
    for (int m = 0; m < 4; m++) { a0[m] = 0ULL; a1[m] = 0ULL; }

    int sw = lane & 15;                  // (lane+32)&15 == lane&15
    const float4* xs0 = (const float4*)Xs + lane * 16;
    const float4* xs1 = (const float4*)Xs + (lane + 32) * 16;

#pragma unroll 1
    for (int i4 = 0; i4 < 16; i4++) {
        int jg = i4 ^ sw;
        float4 xa = xs0[jg];             // conflict-free (swizzled)
        float4 xb = xs1[jg];
        float fa[4] = {xa.x, xa.y, xa.z, xa.w};
        float fb[4] = {xb.x, xb.y, xb.z, xb.w};
#pragma unroll
        for (int kk = 0; kk < 4; kk++) {
            int k = i4 * 4 + kk;
            unsigned long long xx0, xx1;
            asm("mov.b64 %0, {%1, %1};" : "=l"(xx0) : "f"(fa[kk]));
            asm("mov.b64 %0, {%1, %1};" : "=l"(xx1) : "f"(fb[kk]));
            const ulonglong2* wp = (const ulonglong2*)(Ws + k * D + o * 8);
            ulonglong2 w0 = wp[0], w1 = wp[1];          // broadcast LDS.128
            asm("fma.rn.f32x2 %0, %1, %2, %0;" : "+l"(a0[0]) : "l"(xx0), "l"(w0.x));
            asm("fma.rn.f32x2 %0, %1, %2, %0;" : "+l"(a0[1]) : "l"(xx0), "l"(w0.y));
            asm("fma.rn.f32x2 %0, %1, %2, %0;" : "+l"(a0[2]) : "l"(xx0), "l"(w1.x));
            asm("fma.rn.f32x2 %0, %1, %2, %0;" : "+l"(a0[3]) : "l"(xx0), "l"(w1.y));
            asm("fma.rn.f32x2 %0, %1, %2, %0;" : "+l"(a1[0]) : "l"(xx1), "l"(w0.x));
            asm("fma.rn.f32x2 %0, %1, %2, %0;" : "+l"(a1[1]) : "l"(xx1), "l"(w0.y));
            asm("fma.rn.f32x2 %0, %1, %2, %0;" : "+l"(a1[2]) : "l"(xx1), "l"(w1.x));
            asm("fma.rn.f32x2 %0, %1, %2, %0;" : "+l"(a1[3]) : "l"(xx1), "l"(w1.y));
        }
    }

    const float4* brow = (const float4*)(bias + o * 8);   // warp-uniform
    float4 bb0 = __ldg(&brow[0]);
    float4 bb1 = __ldg(&brow[1]);

#pragma unroll
    for (int jn = 0; jn < 2; jn++) {
        int n = (jn == 0) ? n0 : n1;
        if (n >= N) continue;
        unsigned long long* acc = (jn == 0) ? a0 : a1;
        float dv = rsqrtf(g_deg[n]);
        if (o == 0) g_dinv[n] = dv;
        float sl = dv * dv;
        float* hrow = g_h + (size_t)n * D + o * 8;
        float* orow = out + (size_t)n * D + o * 8;
        float f0, f1, f2, f3, f4, f5, f6, f7;
        asm("mov.b64 {%0, %1}, %2;" : "=f"(f0), "=f"(f1) : "l"(acc[0]));
        asm("mov.b64 {%0, %1}, %2;" : "=f"(f2), "=f"(f3) : "l"(acc[1]));
        asm("mov.b64 {%0, %1}, %2;" : "=f"(f4), "=f"(f5) : "l"(acc[2]));
        asm("mov.b64 {%0, %1}, %2;" : "=f"(f6), "=f"(f7) : "l"(acc[3]));
        ((float4*)hrow)[0] = make_float4(f0, f1, f2, f3);
        ((float4*)hrow)[1] = make_float4(f4, f5, f6, f7);
        float4 ov0, ov1;
        ov0.x = fmaf(f0, sl, bb0.x);
        ov0.y = fmaf(f1, sl, bb0.y);
        ov0.z = fmaf(f2, sl, bb0.z);
        ov0.w = fmaf(f3, sl, bb0.w);
        ov1.x = fmaf(f4, sl, bb1.x);
        ov1.y = fmaf(f5, sl, bb1.y);
        ov1.z = fmaf(f6, sl, bb1.z);
        ov1.w = fmaf(f7, sl, bb1.w);
        ((float4*)orow)[0] = ov0;
        ((float4*)orow)[1] = ov1;
    }
}

// ---------------------------------------------------------------------------
// 5) Edge scatter: out[dst] += h[src] * (dinv[src]*dinv[dst])
//    16 threads per edge, one float4 per thread, vector red.
//    (Measured 65 us — REDG LSU-rate floor for atomic formulation.)
// ---------------------------------------------------------------------------
__global__ __launch_bounds__(256)
void scatter_kernel(const int* __restrict__ ei,
                    float* __restrict__ out, int E) {
    long long gid = (long long)blockIdx.x * blockDim.x + threadIdx.x;
    int e = (int)(gid >> 4);
    int l = (int)(gid & 15);
    if (e >= E) return;

    int s = __ldg(&ei[e]);        // src
    int d = __ldg(&ei[E + e]);    // dst
    float norm = g_dinv[s] * g_dinv[d];

    float4 v = ((const float4*)g_h)[(size_t)s * 16 + l];
    v.x *= norm; v.y *= norm; v.z *= norm; v.w *= norm;

    float* o = out + ((size_t)d * D + l * 4);
    asm volatile("red.global.add.v4.f32 [%0], {%1, %2, %3, %4};"
                 :: "l"(o), "f"(v.x), "f"(v.y), "f"(v.z), "f"(v.w)
                 : "memory");
}

// ---------------------------------------------------------------------------
extern "C" void kernel_launch(void* const* d_in, const int* in_sizes, int n_in,
                              void* d_out, int out_size) {
    const float* x  = (const float*)d_in[0];
    const int*   ei = (const int*)d_in[1];
    const float* W  = (const float*)d_in[2];
    const float* b  = (const float*)d_in[3];
    float*       out = (float*)d_out;

    int N = in_sizes[0] / D;   // 100000
    int E = in_sizes[1] / 2;   // 1000000

    int N4 = N / 4;            // N divisible by 4
    deg_init_kernel<<<(N4 + 255) / 256, 256>>>(N4);
    deg_acc_kernel<<<(E + 255) / 256, 256>>>(ei, E);
    wt_kernel<<<16, 256>>>(W);
    gemm_kernel<<<(N + 63) / 64, 256>>>(x, b, out, N);

    long long total = (long long)E * 16;
    int nb_s = (int)((total + 255) / 256);
    scatter_kernel<<<nb_s, 256>>>(ei, out, E);
}